// round 1
// baseline (speedup 1.0000x reference)
#include <cuda_runtime.h>
#include <math.h>

#define D_DIM 512
#define T_DIM 512
#define BT    1024
#define NTHR  512

__device__ float g_energy;

__global__ void k_init() { g_energy = 0.0f; }

__global__ void __launch_bounds__(NTHR) k_main(
    const int*   __restrict__ token_ids,
    const float* __restrict__ resonances,
    const float* __restrict__ emb_scales,
    const float* __restrict__ emb_shifts,
    const float* __restrict__ emb_norm,
    const float* __restrict__ W_enc,
    const float* __restrict__ b_enc,
    const float* __restrict__ W_dec,
    const float* __restrict__ b_dec,
    const float* __restrict__ ecc_strength,
    const float* __restrict__ energy_preservation,
    float* __restrict__ out)
{
    __shared__ double sh_warp[16 * 15];
    __shared__ float  sh_vals[15];
    __shared__ float  sh_c[24];
    __shared__ float  sh_e_in2;
    __shared__ float  sh_red[16];
    __shared__ float  sh_bcast;

    const int tok  = blockIdx.x;
    const int t    = tok & (T_DIM - 1);
    const int d    = threadIdx.x;
    const int wid  = d >> 5;
    const int lane = d & 31;

    // ---- embedding (elementwise, fp32 semantics; trig via double range-reduce) ----
    int   id    = token_ids[tok];
    float tv    = (float)(id % 1000000) / 1000000.0f;
    float angle = resonances[d] * (tv + (float)t);
    double a  = (double)angle;
    double kk = rint(a * 0.15915494309189535);      // 1/(2*pi)
    double r  = fma(-kk, 6.283185307179586, a);     // exact-ish mod 2*pi
    double sd, cd;
    sincos(r, &sd, &cd);
    float s = (float)sd, c = (float)cd;
    float comp = c * (1.0f + s) + s * s;
    float emb  = comp * emb_scales[d] + emb_shifts[d];

    // ---- 15-value reduction: proj_raw[0..11], PA_raw, PB_raw, sum(emb^2) ----
    // Golay structure: ge[k] = proj[k] + (k even ? sum proj{13,15,17,19,21}
    //                                            : sum proj{12,14,16,18,20,22,23})
    const float4* we = (const float4*)(W_enc + d * 24);
    float4 w0 = we[0], w1 = we[1], w2 = we[2], w3 = we[3], w4 = we[4], w5 = we[5];
    double e = (double)emb;
    double v[15];
    v[0] = e * w0.x; v[1] = e * w0.y; v[2]  = e * w0.z; v[3]  = e * w0.w;
    v[4] = e * w1.x; v[5] = e * w1.y; v[6]  = e * w1.z; v[7]  = e * w1.w;
    v[8] = e * w2.x; v[9] = e * w2.y; v[10] = e * w2.z; v[11] = e * w2.w;
    // PA coeff: cols 13,15,17,19,21 ; PB coeff: cols 12,14,16,18,20,22,23
    double pa = (double)w3.y + (double)w3.w + (double)w4.y + (double)w4.w + (double)w5.y;
    double pb = (double)w3.x + (double)w3.z + (double)w4.x + (double)w4.z
              + (double)w5.x + (double)w5.z + (double)w5.w;
    v[12] = e * pa;
    v[13] = e * pb;
    v[14] = e * e;

    #pragma unroll
    for (int j = 0; j < 15; j++) {
        #pragma unroll
        for (int o = 16; o > 0; o >>= 1)
            v[j] += __shfl_xor_sync(0xffffffffu, v[j], o);
    }
    if (lane == 0) {
        #pragma unroll
        for (int j = 0; j < 15; j++) sh_warp[wid * 15 + j] = v[j];
    }
    __syncthreads();
    if (d < 15) {
        double acc = 0.0;
        #pragma unroll
        for (int w = 0; w < 16; w++) acc += sh_warp[w * 15 + d];
        sh_vals[d] = (float)acc;
    }
    __syncthreads();

    // ---- serial lattice encode/decode (tiny: ~150 flops) ----
    if (d == 0) {
        float ecc = ecc_strength[0];
        float ep  = energy_preservation[0];
        float en  = emb_norm[0];
        float tokn = sqrtf(sh_vals[14]);
        float sc   = (tokn > 0.0f) ? (en / tokn) : 1.0f;   // fold normalization (linear)
        float e_in = (tokn > 0.0f) ? en : tokn;            // ||emb_normalized||
        float PA = sc * sh_vals[12]
                 + (b_enc[13] + b_enc[15] + b_enc[17] + b_enc[19] + b_enc[21]);
        float PB = sc * sh_vals[13]
                 + (b_enc[12] + b_enc[14] + b_enc[16] + b_enc[18] + b_enc[20]
                  + b_enc[22] + b_enc[23]);
        float latt[12];
        float ssq_l = 0.0f;
        #pragma unroll
        for (int k = 0; k < 12; k++) {
            float p  = sc * sh_vals[k] + b_enc[k];
            float ge = p + ((k & 1) ? PB : PA);
            float lv = rintf(ge / ecc) * ecc;              // round-half-even, like jnp.round
            latt[k]  = lv;
            ssq_l   += lv * lv;
        }
        float e_out  = sqrtf(ssq_l);
        float scale1 = e_in / (e_out + 1e-8f) * ep;
        float ssq2 = 0.0f, Lodd = 0.0f, Leven = 0.0f;
        #pragma unroll
        for (int k = 0; k < 12; k++) {
            float lv = latt[k] * scale1;
            latt[k]  = lv;
            ssq2    += lv * lv;
            if (k & 1) Lodd += lv; else Leven += lv;
        }
        float e_in2 = sqrtf(ssq2);
        // golay_dec: l<12 -> latt[l]; l in 12..22: even->Lodd, odd->Leven; l=23 -> Lodd
        #pragma unroll
        for (int l = 0; l < 12; l++)
            sh_c[l] = (fabsf(latt[l]) > ecc) ? latt[l] : 0.0f;
        float tO = (fabsf(Lodd)  > ecc) ? Lodd  : 0.0f;
        float tE = (fabsf(Leven) > ecc) ? Leven : 0.0f;
        #pragma unroll
        for (int l = 12; l < 23; l++)
            sh_c[l] = (l & 1) ? tE : tO;
        sh_c[23] = tO;
        sh_e_in2 = e_in2;
    }
    __syncthreads();

    // ---- decode matmul: res[d] = b_dec[d] + sum_l c[l] * W_dec[l][d] ----
    float resv = b_dec[d];
    #pragma unroll
    for (int l = 0; l < 24; l++)
        resv = fmaf(sh_c[l], W_dec[l * D_DIM + d], resv);

    // block reduce resv^2 -> e_out2
    float q = resv * resv;
    #pragma unroll
    for (int o = 16; o > 0; o >>= 1) q += __shfl_xor_sync(0xffffffffu, q, o);
    if (lane == 0) sh_red[wid] = q;
    __syncthreads();
    if (wid == 0) {
        float x = (lane < 16) ? sh_red[lane] : 0.0f;
        #pragma unroll
        for (int o = 8; o > 0; o >>= 1) x += __shfl_xor_sync(0xffffffffu, x, o);
        if (lane == 0) sh_bcast = x;
    }
    __syncthreads();
    float ssqr   = sh_bcast;
    float ep2    = energy_preservation[0];
    float scale2 = sh_e_in2 / (sqrtf(ssqr) + 1e-8f) * ep2;
    out[tok * D_DIM + d] = resv * scale2;

    // global energy accumulation: sum(res_final^2) = scale2^2 * ssqr per token
    if (d == 0) atomicAdd(&g_energy, scale2 * scale2 * ssqr);
}

// fractal branch cancels analytically: result = res * frac_norm * ||res||_F
__global__ void k_scale(float* __restrict__ out, const float* __restrict__ frac_norm)
{
    int   i = blockIdx.x * blockDim.x + threadIdx.x;
    float f = frac_norm[0] * sqrtf(g_energy);
    float4* o = (float4*)out;
    float4 x = o[i];
    x.x *= f; x.y *= f; x.z *= f; x.w *= f;
    o[i] = x;
}

extern "C" void kernel_launch(void* const* d_in, const int* in_sizes, int n_in,
                              void* d_out, int out_size)
{
    const int*   token_ids  = (const int*)  d_in[0];
    const float* resonances = (const float*)d_in[1];
    const float* emb_scales = (const float*)d_in[2];
    const float* emb_shifts = (const float*)d_in[3];
    const float* emb_norm   = (const float*)d_in[4];
    /* d_in[5] scale_weights, d_in[6] fractal_bias: unused (fractal branch cancels) */
    const float* frac_norm  = (const float*)d_in[7];
    const float* W_enc      = (const float*)d_in[8];
    const float* b_enc      = (const float*)d_in[9];
    const float* W_dec      = (const float*)d_in[10];
    const float* b_dec      = (const float*)d_in[11];
    const float* ecc        = (const float*)d_in[12];
    const float* ep         = (const float*)d_in[13];
    float* out = (float*)d_out;

    k_init<<<1, 1>>>();
    k_main<<<BT, NTHR>>>(token_ids, resonances, emb_scales, emb_shifts, emb_norm,
                         W_enc, b_enc, W_dec, b_dec, ecc, ep, out);
    k_scale<<<(BT * D_DIM / 4) / 256, 256>>>(out, frac_norm);
}

// round 2
// speedup vs baseline: 2.0398x; 2.0398x over previous
#include <cuda_runtime.h>
#include <math.h>

#define D_DIM 512
#define T_DIM 512
#define BT    1024

__device__ float g_tok_energy[BT];

__global__ void __launch_bounds__(128) k_main(
    const int*   __restrict__ token_ids,
    const float* __restrict__ resonances,
    const float* __restrict__ emb_scales,
    const float* __restrict__ emb_shifts,
    const float* __restrict__ emb_norm,
    const float* __restrict__ W_enc,
    const float* __restrict__ b_enc,
    const float* __restrict__ W_dec,
    const float* __restrict__ b_dec,
    const float* __restrict__ ecc_strength,
    const float* __restrict__ energy_preservation,
    float* __restrict__ out)
{
    __shared__ double sh_warp[4 * 15];
    __shared__ float  sh_vals[15];
    __shared__ float  sh_c[24];
    __shared__ float  sh_e_in2;
    __shared__ float  sh_red[4];
    __shared__ float  sh_bcast;

    const int tok  = blockIdx.x;
    const int t    = tok & (T_DIM - 1);
    const int tid  = threadIdx.x;
    const int wid  = tid >> 5;
    const int lane = tid & 31;

    // ---- embedding: 4 consecutive d per thread, fp32 semantics identical to ref ----
    int   id   = token_ids[tok];
    float tv   = (float)(id % 1000000) / 1000000.0f;
    float base = tv + (float)t;

    float4 reso = ((const float4*)resonances)[tid];
    float4 escl = ((const float4*)emb_scales)[tid];
    float4 esh  = ((const float4*)emb_shifts)[tid];

    float angv[4] = { reso.x * base, reso.y * base, reso.z * base, reso.w * base };
    float scv[4]  = { escl.x, escl.y, escl.z, escl.w };
    float shv[4]  = { esh.x,  esh.y,  esh.z,  esh.w  };

    float emb[4];
    #pragma unroll
    for (int i = 0; i < 4; i++) {
        // exact-ish mod 2*pi via minimal fp64 (3 ops), then fp32 sincos
        double a  = (double)angv[i];
        double kk = rint(a * 0.15915494309189535);
        float  r  = (float)fma(-kk, 6.283185307179586, a);
        float  s, c;
        __sincosf(r, &s, &c);          // fast approx would risk boundary flips...
        sincosf(r, &s, &c);            // ...so use accurate fp32 path (overwrites)
        float comp = c * (1.0f + s) + s * s;
        emb[i] = comp * scv[i] + shv[i];
    }

    // ---- 15-value reduction: proj_raw[0..11], PA_raw, PB_raw, sum(emb^2) ----
    // Golay structure: ge[k] = proj[k] + (k even ? sum proj{13,15,17,19,21}
    //                                            : sum proj{12,14,16,18,20,22,23})
    double v[15];
    #pragma unroll
    for (int j = 0; j < 15; j++) v[j] = 0.0;

    const float4* we = (const float4*)(W_enc + (size_t)tid * 96);  // rows 4*tid..4*tid+3
    #pragma unroll
    for (int i = 0; i < 4; i++) {
        float4 w0 = we[i*6+0], w1 = we[i*6+1], w2 = we[i*6+2];
        float4 w3 = we[i*6+3], w4 = we[i*6+4], w5 = we[i*6+5];
        double e = (double)emb[i];
        v[0]  = fma(e, (double)w0.x, v[0]);  v[1]  = fma(e, (double)w0.y, v[1]);
        v[2]  = fma(e, (double)w0.z, v[2]);  v[3]  = fma(e, (double)w0.w, v[3]);
        v[4]  = fma(e, (double)w1.x, v[4]);  v[5]  = fma(e, (double)w1.y, v[5]);
        v[6]  = fma(e, (double)w1.z, v[6]);  v[7]  = fma(e, (double)w1.w, v[7]);
        v[8]  = fma(e, (double)w2.x, v[8]);  v[9]  = fma(e, (double)w2.y, v[9]);
        v[10] = fma(e, (double)w2.z, v[10]); v[11] = fma(e, (double)w2.w, v[11]);
        // PA coeff: cols 13,15,17,19,21 ; PB coeff: cols 12,14,16,18,20,22,23
        double pa = (double)w3.y + (double)w3.w + (double)w4.y + (double)w4.w + (double)w5.y;
        double pb = (double)w3.x + (double)w3.z + (double)w4.x + (double)w4.z
                  + (double)w5.x + (double)w5.z + (double)w5.w;
        v[12] = fma(e, pa, v[12]);
        v[13] = fma(e, pb, v[13]);
        v[14] = fma(e, e,  v[14]);
    }

    #pragma unroll
    for (int j = 0; j < 15; j++) {
        #pragma unroll
        for (int o = 16; o > 0; o >>= 1)
            v[j] += __shfl_xor_sync(0xffffffffu, v[j], o);
    }
    if (lane == 0) {
        #pragma unroll
        for (int j = 0; j < 15; j++) sh_warp[wid * 15 + j] = v[j];
    }
    __syncthreads();
    if (tid < 15) {
        double acc = sh_warp[tid] + sh_warp[15 + tid] + sh_warp[30 + tid] + sh_warp[45 + tid];
        sh_vals[tid] = (float)acc;
    }
    __syncthreads();

    // ---- serial lattice encode/decode (tiny: ~150 flops) ----
    if (tid == 0) {
        float ecc = ecc_strength[0];
        float ep  = energy_preservation[0];
        float en  = emb_norm[0];
        float tokn = sqrtf(sh_vals[14]);
        float sc   = (tokn > 0.0f) ? (en / tokn) : 1.0f;   // fold normalization (linear)
        float e_in = (tokn > 0.0f) ? en : tokn;            // ||emb_normalized||
        float PA = sc * sh_vals[12]
                 + (b_enc[13] + b_enc[15] + b_enc[17] + b_enc[19] + b_enc[21]);
        float PB = sc * sh_vals[13]
                 + (b_enc[12] + b_enc[14] + b_enc[16] + b_enc[18] + b_enc[20]
                  + b_enc[22] + b_enc[23]);
        float latt[12];
        float ssq_l = 0.0f;
        #pragma unroll
        for (int k = 0; k < 12; k++) {
            float p  = sc * sh_vals[k] + b_enc[k];
            float ge = p + ((k & 1) ? PB : PA);
            float lv = rintf(ge / ecc) * ecc;              // round-half-even, like jnp.round
            latt[k]  = lv;
            ssq_l   += lv * lv;
        }
        float e_out  = sqrtf(ssq_l);
        float scale1 = e_in / (e_out + 1e-8f) * ep;
        float ssq2 = 0.0f, Lodd = 0.0f, Leven = 0.0f;
        #pragma unroll
        for (int k = 0; k < 12; k++) {
            float lv = latt[k] * scale1;
            latt[k]  = lv;
            ssq2    += lv * lv;
            if (k & 1) Lodd += lv; else Leven += lv;
        }
        float e_in2 = sqrtf(ssq2);
        // golay_dec: l<12 -> latt[l]; l in 12..22: even->Lodd, odd->Leven; l=23 -> Lodd
        #pragma unroll
        for (int l = 0; l < 12; l++)
            sh_c[l] = (fabsf(latt[l]) > ecc) ? latt[l] : 0.0f;
        float tO = (fabsf(Lodd)  > ecc) ? Lodd  : 0.0f;
        float tE = (fabsf(Leven) > ecc) ? Leven : 0.0f;
        #pragma unroll
        for (int l = 12; l < 23; l++)
            sh_c[l] = (l & 1) ? tE : tO;
        sh_c[23] = tO;
        sh_e_in2 = e_in2;
    }
    __syncthreads();

    // ---- decode matmul: res[d0..d0+3] = b_dec + sum_l c[l] * W_dec[l][d0..d0+3] ----
    float cc[24];
    #pragma unroll
    for (int l = 0; l < 24; l++) cc[l] = sh_c[l];

    float4 r4 = ((const float4*)b_dec)[tid];
    #pragma unroll
    for (int l = 0; l < 24; l++) {
        float4 w = ((const float4*)(W_dec + (size_t)l * D_DIM))[tid];
        r4.x = fmaf(cc[l], w.x, r4.x);
        r4.y = fmaf(cc[l], w.y, r4.y);
        r4.z = fmaf(cc[l], w.z, r4.z);
        r4.w = fmaf(cc[l], w.w, r4.w);
    }

    // block reduce sum(res^2) -> e_out2
    float q = r4.x * r4.x + r4.y * r4.y + r4.z * r4.z + r4.w * r4.w;
    #pragma unroll
    for (int o = 16; o > 0; o >>= 1) q += __shfl_xor_sync(0xffffffffu, q, o);
    if (lane == 0) sh_red[wid] = q;
    __syncthreads();
    if (tid == 0)
        sh_bcast = sh_red[0] + sh_red[1] + sh_red[2] + sh_red[3];
    __syncthreads();

    float ssqr   = sh_bcast;
    float ep2    = energy_preservation[0];
    float scale2 = sh_e_in2 / (sqrtf(ssqr) + 1e-8f) * ep2;

    float4 o4;
    o4.x = r4.x * scale2; o4.y = r4.y * scale2;
    o4.z = r4.z * scale2; o4.w = r4.w * scale2;
    ((float4*)out)[tok * (D_DIM / 4) + tid] = o4;

    // per-token final energy: sum(res_final^2) = scale2^2 * ssqr
    if (tid == 0) g_tok_energy[tok] = scale2 * scale2 * ssqr;
}

// fractal branch cancels analytically: result = res * frac_norm * ||res||_F.
// Every block redundantly reduces the 1024-float energy array (L2-hot) — no
// extra kernel, fully deterministic.
__global__ void __launch_bounds__(256) k_scale(float* __restrict__ out,
                                               const float* __restrict__ frac_norm)
{
    __shared__ float sh_red[8];
    __shared__ float sh_f;
    const int tid  = threadIdx.x;
    const int wid  = tid >> 5;
    const int lane = tid & 31;

    float4 e4 = ((const float4*)g_tok_energy)[tid];   // 256 threads x 4 = 1024
    float  e  = e4.x + e4.y + e4.z + e4.w;
    #pragma unroll
    for (int o = 16; o > 0; o >>= 1) e += __shfl_xor_sync(0xffffffffu, e, o);
    if (lane == 0) sh_red[wid] = e;
    __syncthreads();
    if (tid == 0) {
        float tot = 0.0f;
        #pragma unroll
        for (int w = 0; w < 8; w++) tot += sh_red[w];
        sh_f = frac_norm[0] * sqrtf(tot);
    }
    __syncthreads();

    float  f = sh_f;
    int    i = blockIdx.x * 256 + tid;
    float4* o = (float4*)out;
    float4 x = o[i];
    x.x *= f; x.y *= f; x.z *= f; x.w *= f;
    o[i] = x;
}

extern "C" void kernel_launch(void* const* d_in, const int* in_sizes, int n_in,
                              void* d_out, int out_size)
{
    const int*   token_ids  = (const int*)  d_in[0];
    const float* resonances = (const float*)d_in[1];
    const float* emb_scales = (const float*)d_in[2];
    const float* emb_shifts = (const float*)d_in[3];
    const float* emb_norm   = (const float*)d_in[4];
    /* d_in[5] scale_weights, d_in[6] fractal_bias: unused (fractal branch cancels) */
    const float* frac_norm  = (const float*)d_in[7];
    const float* W_enc      = (const float*)d_in[8];
    const float* b_enc      = (const float*)d_in[9];
    const float* W_dec      = (const float*)d_in[10];
    const float* b_dec      = (const float*)d_in[11];
    const float* ecc        = (const float*)d_in[12];
    const float* ep         = (const float*)d_in[13];
    float* out = (float*)d_out;

    k_main<<<BT, 128>>>(token_ids, resonances, emb_scales, emb_shifts, emb_norm,
                        W_enc, b_enc, W_dec, b_dec, ecc, ep, out);
    k_scale<<<(BT * D_DIM / 4) / 256, 256>>>(out, frac_norm);
}